// round 1
// baseline (speedup 1.0000x reference)
#include <cuda_runtime.h>

#define B_  8
#define C_  64
#define CO_ 64
#define H_  128
#define W_  128
#define HW_ (H_*W_)

// Scratch (device globals — no allocation allowed)
__device__ __align__(16) float g_off[B_*4*HW_];      // offsets o[b][4][h][w]
__device__ __align__(16) float g_wT[9*C_*CO_];       // weight transposed [k][c][o]

__constant__ int c_dysel[9] = {0,1,4,0,1,2,4,4,3};   // 0=t 1=b 2=l 3=r 4=zero
__constant__ int c_dxsel[9] = {4,0,1,4,2,2,4,3,3};

// ---------------------------------------------------------------- weight transpose
__global__ void wT_kernel(const float* __restrict__ weight) {
    int idx = blockIdx.x*256 + threadIdx.x;
    if (idx < 9*C_*CO_) {
        int k = idx / (C_*CO_);
        int r = idx % (C_*CO_);
        int c = r / CO_;
        int o = r % CO_;
        g_wT[idx] = weight[(o*C_ + c)*9 + k];
    }
}

// ---------------------------------------------------------------- offset conv (4 out ch)
__global__ void offset_kernel(const float* __restrict__ x,
                              const float* __restrict__ ow,
                              const float* __restrict__ ob) {
    __shared__ float ws[4*C_*9];
    int b = blockIdx.x >> 7;
    int h = blockIdx.x & 127;
    int t = threadIdx.x;               // 128 threads: one per w
    for (int i = t; i < 4*C_*9; i += 128) ws[i] = ow[i];
    __syncthreads();

    float a0 = ob[0], a1 = ob[1], a2 = ob[2], a3 = ob[3];
    const float* xb = x + (size_t)b*C_*HW_;
    int w = t;
    for (int c = 0; c < C_; c++) {
        const float* xp = xb + c*HW_;
        #pragma unroll
        for (int i = 0; i < 3; i++) {
            int y = h - 1 + i;
            if ((unsigned)y >= (unsigned)H_) continue;
            #pragma unroll
            for (int j = 0; j < 3; j++) {
                int xx = w - 1 + j;
                if ((unsigned)xx >= (unsigned)W_) continue;
                float v = xp[y*W_ + xx];
                int kk = i*3 + j;
                a0 += v * ws[(0*C_ + c)*9 + kk];
                a1 += v * ws[(1*C_ + c)*9 + kk];
                a2 += v * ws[(2*C_ + c)*9 + kk];
                a3 += v * ws[(3*C_ + c)*9 + kk];
            }
        }
    }
    int base = ((b*4 + 0)*H_ + h)*W_ + w;
    g_off[base]          = a0;
    g_off[base +   HW_]  = a1;
    g_off[base + 2*HW_]  = a2;
    g_off[base + 3*HW_]  = a3;
}

// ---------------------------------------------------------------- main fused deformable conv
// smem layout (floats): wS [9*64*64)=36864 | sS [8192) | cS [512) | aS(int) [512)
#define SMEM_FLOATS (36864 + 8192 + 512 + 512)

__device__ __forceinline__ float selo(int s, float t, float b, float l, float r) {
    switch (s) {
        case 0: return t;
        case 1: return b;
        case 2: return l;
        case 3: return r;
        default: return 0.f;
    }
}

__global__ void __launch_bounds__(256, 1)
main_kernel(const float* __restrict__ x, float* __restrict__ out) {
    extern __shared__ float smem[];
    float* wS = smem;                         // 36864 floats
    float* sS = smem + 36864;                 // 8192 floats  [c][w]
    float* cS = smem + 36864 + 8192;          // 512 floats   [4][128]
    int*   aS = (int*)(smem + 36864 + 8192 + 512); // 512 ints [4][128]

    int b = blockIdx.x >> 7;
    int h = blockIdx.x & 127;
    int t = threadIdx.x;
    int wg = t & 31;       // 4-wide w group
    int og = t >> 5;       // 8-wide o group

    // Stage all weights into smem
    {
        float4* dst = (float4*)wS;
        const float4* src = (const float4*)g_wT;
        for (int i = t; i < (9*C_*CO_)/4; i += 256) dst[i] = src[i];
    }

    const float* xb = x + (size_t)b*C_*HW_;

    // Per-row offsets (threads 0..127, one per w)
    float o_t = 0.f, o_b = 0.f, o_l = 0.f, o_r = 0.f;
    if (t < 128) {
        int base = ((b*4 + 0)*H_ + h)*W_ + t;
        o_t = g_off[base];
        o_b = g_off[base +   HW_];
        o_l = g_off[base + 2*HW_];
        o_r = g_off[base + 3*HW_];
    }

    float4 acc[8];
    #pragma unroll
    for (int i = 0; i < 8; i++) acc[i] = make_float4(0.f, 0.f, 0.f, 0.f);

    #pragma unroll 1
    for (int k = 0; k < 9; k++) {
        __syncthreads();   // protect sS/coeff from previous tap's readers (and wS load at k=0)

        // ---- Phase A: bilinear coefficients per position (threads 0..127) ----
        if (t < 128) {
            int ki = k / 3, kj = k % 3;
            float dy = selo(c_dysel[k], o_t, o_b, o_l, o_r);
            float dx = selo(c_dxsel[k], o_t, o_b, o_l, o_r);
            float py = (float)(h - 1 + ki) + dy;
            float px = (float)(t - 1 + kj) + dx;
            float y0f = floorf(py), x0f = floorf(px);
            float ly = py - y0f,   lx = px - x0f;
            int y0 = (int)y0f, x0 = (int)x0f;
            int y1 = y0 + 1,   x1 = x0 + 1;
            float vy0 = (y0 >= 0 && y0 < H_) ? 1.f : 0.f;
            float vy1 = (y1 >= 0 && y1 < H_) ? 1.f : 0.f;
            float vx0 = (x0 >= 0 && x0 < W_) ? 1.f : 0.f;
            float vx1 = (x1 >= 0 && x1 < W_) ? 1.f : 0.f;
            int cy0 = min(max(y0, 0), H_-1), cy1 = min(max(y1, 0), H_-1);
            int cx0 = min(max(x0, 0), W_-1), cx1 = min(max(x1, 0), W_-1);
            aS[0*128 + t] = cy0*W_ + cx0;
            aS[1*128 + t] = cy0*W_ + cx1;
            aS[2*128 + t] = cy1*W_ + cx0;
            aS[3*128 + t] = cy1*W_ + cx1;
            cS[0*128 + t] = (1.f-ly)*(1.f-lx)*vy0*vx0;
            cS[1*128 + t] = (1.f-ly)*lx      *vy0*vx1;
            cS[2*128 + t] = ly*(1.f-lx)      *vy1*vx0;
            cS[3*128 + t] = ly*lx            *vy1*vx1;
        }
        __syncthreads();

        // ---- Phase B: gather samples into sS[c][w] ----
        #pragma unroll 4
        for (int i = 0; i < 32; i++) {
            int idx = t + 256*i;
            int c = idx >> 7;
            int w = idx & 127;
            const float* xp = xb + c*HW_;
            float v = cS[      w] * xp[aS[      w]]
                    + cS[128 + w] * xp[aS[128 + w]]
                    + cS[256 + w] * xp[aS[256 + w]]
                    + cS[384 + w] * xp[aS[384 + w]];
            sS[idx] = v;
        }
        __syncthreads();

        // ---- Phase C: register-blocked GEMM accumulate ----
        const float4* sv4 = (const float4*)sS;                   // [c*32 + wg]
        const float*  wkp = wS + (k*C_)*CO_ + og*8;              // + c*64 per c
        #pragma unroll 4
        for (int c = 0; c < C_; c++) {
            float4 s  = sv4[c*32 + wg];
            float4 wa = *(const float4*)(wkp + c*CO_);
            float4 wb = *(const float4*)(wkp + c*CO_ + 4);
            acc[0].x += wa.x*s.x; acc[0].y += wa.x*s.y; acc[0].z += wa.x*s.z; acc[0].w += wa.x*s.w;
            acc[1].x += wa.y*s.x; acc[1].y += wa.y*s.y; acc[1].z += wa.y*s.z; acc[1].w += wa.y*s.w;
            acc[2].x += wa.z*s.x; acc[2].y += wa.z*s.y; acc[2].z += wa.z*s.z; acc[2].w += wa.z*s.w;
            acc[3].x += wa.w*s.x; acc[3].y += wa.w*s.y; acc[3].z += wa.w*s.z; acc[3].w += wa.w*s.w;
            acc[4].x += wb.x*s.x; acc[4].y += wb.x*s.y; acc[4].z += wb.x*s.z; acc[4].w += wb.x*s.w;
            acc[5].x += wb.y*s.x; acc[5].y += wb.y*s.y; acc[5].z += wb.y*s.z; acc[5].w += wb.y*s.w;
            acc[6].x += wb.z*s.x; acc[6].y += wb.z*s.y; acc[6].z += wb.z*s.z; acc[6].w += wb.z*s.w;
            acc[7].x += wb.w*s.x; acc[7].y += wb.w*s.y; acc[7].z += wb.w*s.z; acc[7].w += wb.w*s.w;
        }
    }

    // ---- Write out: out[b][og*8+oi][h][wg*4 .. +3] ----
    size_t wbase = (((size_t)b*CO_ + og*8)*H_ + h)*W_ + wg*4;
    #pragma unroll
    for (int oi = 0; oi < 8; oi++) {
        *(float4*)(out + wbase + (size_t)oi*HW_) = acc[oi];
    }
}

// ---------------------------------------------------------------- launch
extern "C" void kernel_launch(void* const* d_in, const int* in_sizes, int n_in,
                              void* d_out, int out_size) {
    const float* x  = (const float*)d_in[0];   // (8,64,128,128)
    const float* ow = (const float*)d_in[1];   // (4,64,3,3)
    const float* ob = (const float*)d_in[2];   // (4,)
    const float* wt = (const float*)d_in[3];   // (64,64,3,3)
    float* out = (float*)d_out;                // (8,64,128,128)

    cudaFuncSetAttribute(main_kernel, cudaFuncAttributeMaxDynamicSharedMemorySize,
                         SMEM_FLOATS * (int)sizeof(float));

    wT_kernel<<<(9*C_*CO_ + 255)/256, 256>>>(wt);
    offset_kernel<<<B_*H_, 128>>>(x, ow, ob);
    main_kernel<<<B_*H_, 256, SMEM_FLOATS * sizeof(float)>>>(x, out);
}

// round 2
// speedup vs baseline: 1.5934x; 1.5934x over previous
#include <cuda_runtime.h>

#define B_  8
#define C_  64
#define CO_ 64
#define H_  128
#define W_  128
#define HW_ (H_*W_)

// Scratch (device globals — no allocation allowed)
__device__ __align__(16) float g_off[B_*4*HW_];      // offsets o[b][4][h][w]
__device__ __align__(16) float g_wT[9*C_*CO_];       // weight transposed [k][c][o]

__constant__ int c_dysel[9] = {0,1,4,0,1,2,4,4,3};   // 0=t 1=b 2=l 3=r 4=zero
__constant__ int c_dxsel[9] = {4,0,1,4,2,2,4,3,3};

// packed fp32x2 FMA (SASS FFMA2) — PTX-only, ptxas never auto-fuses
#define FMA2(d,a,b) asm("fma.rn.f32x2 %0, %1, %2, %0;" : "+l"(d) : "l"(a), "l"(b))
#define PACK_DUP(d,f) asm("mov.b64 %0, {%1, %1};" : "=l"(d) : "r"(__float_as_uint(f)))

// ---------------------------------------------------------------- weight transpose
__global__ void wT_kernel(const float* __restrict__ weight) {
    int idx = blockIdx.x*256 + threadIdx.x;
    if (idx < 9*C_*CO_) {
        int k = idx / (C_*CO_);
        int r = idx % (C_*CO_);
        int c = r / CO_;
        int o = r % CO_;
        g_wT[idx] = weight[(o*C_ + c)*9 + k];
    }
}

// ---------------------------------------------------------------- offset conv (4 out ch)
__global__ void offset_kernel(const float* __restrict__ x,
                              const float* __restrict__ ow,
                              const float* __restrict__ ob) {
    __shared__ float ws[4*C_*9];
    int b = blockIdx.x >> 7;
    int h = blockIdx.x & 127;
    int t = threadIdx.x;               // 128 threads: one per w
    for (int i = t; i < 4*C_*9; i += 128) ws[i] = ow[i];
    __syncthreads();

    float a0 = ob[0], a1 = ob[1], a2 = ob[2], a3 = ob[3];
    const float* xb = x + (size_t)b*C_*HW_;
    int w = t;
    for (int c = 0; c < C_; c++) {
        const float* xp = xb + c*HW_;
        #pragma unroll
        for (int i = 0; i < 3; i++) {
            int y = h - 1 + i;
            if ((unsigned)y >= (unsigned)H_) continue;
            #pragma unroll
            for (int j = 0; j < 3; j++) {
                int xx = w - 1 + j;
                if ((unsigned)xx >= (unsigned)W_) continue;
                float v = xp[y*W_ + xx];
                int kk = i*3 + j;
                a0 += v * ws[(0*C_ + c)*9 + kk];
                a1 += v * ws[(1*C_ + c)*9 + kk];
                a2 += v * ws[(2*C_ + c)*9 + kk];
                a3 += v * ws[(3*C_ + c)*9 + kk];
            }
        }
    }
    int base = ((b*4 + 0)*H_ + h)*W_ + w;
    g_off[base]          = a0;
    g_off[base +   HW_]  = a1;
    g_off[base + 2*HW_]  = a2;
    g_off[base + 3*HW_]  = a3;
}

// ---------------------------------------------------------------- main fused deformable conv
// smem layout (floats): wS [36864) | sS double buffer [2*8192) | cS [512) | aS(int) [512)
#define SMEM_FLOATS (36864 + 16384 + 512 + 512)

__device__ __forceinline__ float selo(int s, float t, float b, float l, float r) {
    switch (s) {
        case 0: return t;
        case 1: return b;
        case 2: return l;
        case 3: return r;
        default: return 0.f;
    }
}

__device__ __forceinline__ void phaseA(int k, int h, int t,
                                       float o_t, float o_b, float o_l, float o_r,
                                       float* cS, int* aS) {
    int ki = k / 3, kj = k % 3;
    float dy = selo(c_dysel[k], o_t, o_b, o_l, o_r);
    float dx = selo(c_dxsel[k], o_t, o_b, o_l, o_r);
    float py = (float)(h - 1 + ki) + dy;
    float px = (float)(t - 1 + kj) + dx;
    float y0f = floorf(py), x0f = floorf(px);
    float ly = py - y0f,   lx = px - x0f;
    int y0 = (int)y0f, x0 = (int)x0f;
    int y1 = y0 + 1,   x1 = x0 + 1;
    float vy0 = (y0 >= 0 && y0 < H_) ? 1.f : 0.f;
    float vy1 = (y1 >= 0 && y1 < H_) ? 1.f : 0.f;
    float vx0 = (x0 >= 0 && x0 < W_) ? 1.f : 0.f;
    float vx1 = (x1 >= 0 && x1 < W_) ? 1.f : 0.f;
    int cy0 = min(max(y0, 0), H_-1), cy1 = min(max(y1, 0), H_-1);
    int cx0 = min(max(x0, 0), W_-1), cx1 = min(max(x1, 0), W_-1);
    aS[0*128 + t] = cy0*W_ + cx0;
    aS[1*128 + t] = cy0*W_ + cx1;
    aS[2*128 + t] = cy1*W_ + cx0;
    aS[3*128 + t] = cy1*W_ + cx1;
    cS[0*128 + t] = (1.f-ly)*(1.f-lx)*vy0*vx0;
    cS[1*128 + t] = (1.f-ly)*lx      *vy0*vx1;
    cS[2*128 + t] = ly*(1.f-lx)      *vy1*vx0;
    cS[3*128 + t] = ly*lx            *vy1*vx1;
}

__global__ void __launch_bounds__(256, 1)
main_kernel(const float* __restrict__ x, float* __restrict__ out) {
    extern __shared__ float smem[];
    float* wS = smem;                          // 36864 floats
    float* sS = smem + 36864;                  // 2 * 8192 floats  [buf][c][w]
    float* cS = smem + 36864 + 16384;          // 512 floats   [4][128]
    int*   aS = (int*)(cS + 512);              // 512 ints     [4][128]

    int b = blockIdx.x >> 7;
    int h = blockIdx.x & 127;
    int t = threadIdx.x;
    int wg = t & 31;       // 4-wide w group (lane)
    int og = t >> 5;       // 8-wide o group (warp)
    int w  = t & 127;      // gather w position (fixed per thread)
    int cbase = t >> 7;    // gather channel base (0 or 1)

    // Stage all weights into smem
    {
        float4* dst = (float4*)wS;
        const float4* src = (const float4*)g_wT;
        for (int i = t; i < (9*C_*CO_)/4; i += 256) dst[i] = src[i];
    }

    const float* xb = x + (size_t)b*C_*HW_;

    // Per-row offsets (threads 0..127, one per w)
    float o_t = 0.f, o_b = 0.f, o_l = 0.f, o_r = 0.f;
    if (t < 128) {
        int base = ((b*4 + 0)*H_ + h)*W_ + t;
        o_t = g_off[base];
        o_b = g_off[base +   HW_];
        o_l = g_off[base + 2*HW_];
        o_r = g_off[base + 3*HW_];
    }

    // accumulators: acc[p][j] = packed f32x2 (o = og*8+2p lo, og*8+2p+1 hi) at w = wg*4+j
    unsigned long long acc[4][4];
    #pragma unroll
    for (int p = 0; p < 4; p++)
        #pragma unroll
        for (int j = 0; j < 4; j++) acc[p][j] = 0ull;

    // ---- prologue: A(0) + pipelined gather of tap 0 into sS[0] ----
    if (t < 128) phaseA(0, h, t, o_t, o_b, o_l, o_r, cS, aS);
    __syncthreads();
    {
        float cc0 = cS[w], cc1 = cS[128+w], cc2 = cS[256+w], cc3 = cS[384+w];
        int   ia0 = aS[w], ia1 = aS[128+w], ia2 = aS[256+w], ia3 = aS[384+w];
        float pr[16];
        #pragma unroll 4
        for (int c = 0; c < 36; c++) {
            int slot = (c & 3) * 4;
            if (c >= 4) {
                int cg = cbase + 2*(c-4);
                sS[cg*128 + w] = cc0*pr[slot] + cc1*pr[slot+1] + cc2*pr[slot+2] + cc3*pr[slot+3];
            }
            if (c < 32) {
                const float* xp = xb + (size_t)(cbase + 2*c)*HW_;
                pr[slot]   = xp[ia0];
                pr[slot+1] = xp[ia1];
                pr[slot+2] = xp[ia2];
                pr[slot+3] = xp[ia3];
            }
        }
    }

    int cur = 0;
    #pragma unroll 1
    for (int k = 0; k < 9; k++) {
        __syncthreads();   // sS[cur] for tap k ready; cS/aS free for reuse
        bool act = (k < 8);
        if (act && t < 128) phaseA(k+1, h, t, o_t, o_b, o_l, o_r, cS, aS);
        __syncthreads();   // coeffs for tap k+1 visible

        float cc0 = 0.f, cc1 = 0.f, cc2 = 0.f, cc3 = 0.f;
        int   ia0 = 0,   ia1 = 0,   ia2 = 0,   ia3 = 0;
        if (act) {
            cc0 = cS[w]; cc1 = cS[128+w]; cc2 = cS[256+w]; cc3 = cS[384+w];
            ia0 = aS[w]; ia1 = aS[128+w]; ia2 = aS[256+w]; ia3 = aS[384+w];
        }
        const float4* sv4 = (const float4*)(sS + cur*8192);
        float*        sN  = sS + (cur^1)*8192;
        const float*  wk  = wS + k*(C_*CO_) + og*8;
        float pr[16];

        // merged loop: GEMM(tap k) + distance-4-pipelined gather(tap k+1)
        #pragma unroll 4
        for (int c = 0; c < 64; c++) {
            int slot = (c & 3) * 4;
            if (act) {
                if (c >= 4 && c < 36) {
                    int cg = cbase + 2*(c-4);
                    sN[cg*128 + w] = cc0*pr[slot] + cc1*pr[slot+1] + cc2*pr[slot+2] + cc3*pr[slot+3];
                }
                if (c < 32) {
                    const float* xp = xb + (size_t)(cbase + 2*c)*HW_;
                    pr[slot]   = xp[ia0];
                    pr[slot+1] = xp[ia1];
                    pr[slot+2] = xp[ia2];
                    pr[slot+3] = xp[ia3];
                }
            }
            // ---- GEMM c-iter (f32x2 packed) ----
            float4 s = sv4[c*32 + wg];
            const ulonglong2* wp2 = (const ulonglong2*)(wk + c*CO_);
            ulonglong2 wpa = wp2[0];   // packs (w_o0,w_o1),(w_o2,w_o3)
            ulonglong2 wpb = wp2[1];   // packs (w_o4,w_o5),(w_o6,w_o7)
            unsigned long long sd0, sd1, sd2, sd3;
            PACK_DUP(sd0, s.x); PACK_DUP(sd1, s.y); PACK_DUP(sd2, s.z); PACK_DUP(sd3, s.w);
            FMA2(acc[0][0], wpa.x, sd0); FMA2(acc[0][1], wpa.x, sd1);
            FMA2(acc[0][2], wpa.x, sd2); FMA2(acc[0][3], wpa.x, sd3);
            FMA2(acc[1][0], wpa.y, sd0); FMA2(acc[1][1], wpa.y, sd1);
            FMA2(acc[1][2], wpa.y, sd2); FMA2(acc[1][3], wpa.y, sd3);
            FMA2(acc[2][0], wpb.x, sd0); FMA2(acc[2][1], wpb.x, sd1);
            FMA2(acc[2][2], wpb.x, sd2); FMA2(acc[2][3], wpb.x, sd3);
            FMA2(acc[3][0], wpb.y, sd0); FMA2(acc[3][1], wpb.y, sd1);
            FMA2(acc[3][2], wpb.y, sd2); FMA2(acc[3][3], wpb.y, sd3);
        }
        cur ^= 1;
    }

    // ---- write out: out[b][o][h][w], o = og*8 + 2p (lo) / 2p+1 (hi), w = wg*4+j ----
    size_t obase = (((size_t)b*CO_ + og*8)*H_ + h)*W_ + wg*4;
    #pragma unroll
    for (int p = 0; p < 4; p++) {
        float4 lo4, hi4;
        lo4.x = __uint_as_float((unsigned)(acc[p][0]));
        lo4.y = __uint_as_float((unsigned)(acc[p][1]));
        lo4.z = __uint_as_float((unsigned)(acc[p][2]));
        lo4.w = __uint_as_float((unsigned)(acc[p][3]));
        hi4.x = __uint_as_float((unsigned)(acc[p][0] >> 32));
        hi4.y = __uint_as_float((unsigned)(acc[p][1] >> 32));
        hi4.z = __uint_as_float((unsigned)(acc[p][2] >> 32));
        hi4.w = __uint_as_float((unsigned)(acc[p][3] >> 32));
        *(float4*)(out + obase + (size_t)(2*p    )*HW_) = lo4;
        *(float4*)(out + obase + (size_t)(2*p + 1)*HW_) = hi4;
    }
}

// ---------------------------------------------------------------- launch
extern "C" void kernel_launch(void* const* d_in, const int* in_sizes, int n_in,
                              void* d_out, int out_size) {
    const float* x  = (const float*)d_in[0];   // (8,64,128,128)
    const float* ow = (const float*)d_in[1];   // (4,64,3,3)
    const float* ob = (const float*)d_in[2];   // (4,)
    const float* wt = (const float*)d_in[3];   // (64,64,3,3)
    float* out = (float*)d_out;                // (8,64,128,128)

    cudaFuncSetAttribute(main_kernel, cudaFuncAttributeMaxDynamicSharedMemorySize,
                         SMEM_FLOATS * (int)sizeof(float));

    wT_kernel<<<(9*C_*CO_ + 255)/256, 256>>>(wt);
    offset_kernel<<<B_*H_, 128>>>(x, ow, ob);
    main_kernel<<<B_*H_, 256, SMEM_FLOATS * sizeof(float)>>>(x, out);
}

// round 3
// speedup vs baseline: 1.8533x; 1.1631x over previous
#include <cuda_runtime.h>

#define B_  8
#define C_  64
#define CO_ 64
#define H_  128
#define W_  128
#define HW_ (H_*W_)

// Scratch (device globals — no allocation allowed)
__device__ __align__(16) float g_off[B_*4*HW_];      // offsets o[b][4][h][w]
__device__ __align__(16) float g_wT[9*C_*CO_];       // weight transposed [k][c][o]

__constant__ int c_dysel[9] = {0,1,4,0,1,2,4,4,3};   // 0=t 1=b 2=l 3=r 4=zero
__constant__ int c_dxsel[9] = {4,0,1,4,2,2,4,3,3};

// packed fp32x2 FMA (SASS FFMA2) — PTX-only, ptxas never auto-fuses
#define FMA2(d,a,b) asm("fma.rn.f32x2 %0, %1, %2, %0;" : "+l"(d) : "l"(a), "l"(b))
#define PACK_DUP(d,f) asm("mov.b64 %0, {%1, %1};" : "=l"(d) : "r"(__float_as_uint(f)))

// cp.async 16B global->shared (no register cost, async completion)
#define CP_ASYNC16(saddr, gptr) \
    asm volatile("cp.async.cg.shared.global [%0], [%1], 16;" :: "r"(saddr), "l"(gptr) : "memory")
#define CP_COMMIT() asm volatile("cp.async.commit_group;" ::: "memory")
#define CP_WAIT0()  asm volatile("cp.async.wait_group 0;" ::: "memory")

// ---------------------------------------------------------------- weight transpose
__global__ void wT_kernel(const float* __restrict__ weight) {
    int idx = blockIdx.x*256 + threadIdx.x;
    if (idx < 9*C_*CO_) {
        int k = idx / (C_*CO_);
        int r = idx % (C_*CO_);
        int c = r / CO_;
        int o = r % CO_;
        g_wT[idx] = weight[(o*C_ + c)*9 + k];
    }
}

// ---------------------------------------------------------------- offset conv (4 out ch)
__global__ void offset_kernel(const float* __restrict__ x,
                              const float* __restrict__ ow,
                              const float* __restrict__ ob) {
    __shared__ float ws[4*C_*9];
    int b = blockIdx.x >> 7;
    int h = blockIdx.x & 127;
    int t = threadIdx.x;               // 128 threads: one per w
    for (int i = t; i < 4*C_*9; i += 128) ws[i] = ow[i];
    __syncthreads();

    float a0 = ob[0], a1 = ob[1], a2 = ob[2], a3 = ob[3];
    const float* xb = x + (size_t)b*C_*HW_;
    int w = t;
    for (int c = 0; c < C_; c++) {
        const float* xp = xb + c*HW_;
        #pragma unroll
        for (int i = 0; i < 3; i++) {
            int y = h - 1 + i;
            if ((unsigned)y >= (unsigned)H_) continue;
            #pragma unroll
            for (int j = 0; j < 3; j++) {
                int xx = w - 1 + j;
                if ((unsigned)xx >= (unsigned)W_) continue;
                float v = xp[y*W_ + xx];
                int kk = i*3 + j;
                a0 += v * ws[(0*C_ + c)*9 + kk];
                a1 += v * ws[(1*C_ + c)*9 + kk];
                a2 += v * ws[(2*C_ + c)*9 + kk];
                a3 += v * ws[(3*C_ + c)*9 + kk];
            }
        }
    }
    int base = ((b*4 + 0)*H_ + h)*W_ + w;
    g_off[base]          = a0;
    g_off[base +   HW_]  = a1;
    g_off[base + 2*HW_]  = a2;
    g_off[base + 3*HW_]  = a3;
}

// ---------------------------------------------------------------- main fused deformable conv
// smem (floats): wS double [2*4096) | sS double [2*8192) | cS [512) | aS(int) [512)
#define WS_OFF  0
#define SS_OFF  8192
#define CS_OFF  24576
#define AS_OFF  25088
#define SMEM_FLOATS 25600   // 100 KB -> 2 CTAs/SM

__device__ __forceinline__ float selo(int s, float t, float b, float l, float r) {
    switch (s) {
        case 0: return t;
        case 1: return b;
        case 2: return l;
        case 3: return r;
        default: return 0.f;
    }
}

__device__ __forceinline__ void phaseA(int k, int h, int t,
                                       float o_t, float o_b, float o_l, float o_r,
                                       float* cS, int* aS) {
    int ki = k / 3, kj = k % 3;
    float dy = selo(c_dysel[k], o_t, o_b, o_l, o_r);
    float dx = selo(c_dxsel[k], o_t, o_b, o_l, o_r);
    float py = (float)(h - 1 + ki) + dy;
    float px = (float)(t - 1 + kj) + dx;
    float y0f = floorf(py), x0f = floorf(px);
    float ly = py - y0f,   lx = px - x0f;
    int y0 = (int)y0f, x0 = (int)x0f;
    int y1 = y0 + 1,   x1 = x0 + 1;
    float vy0 = (y0 >= 0 && y0 < H_) ? 1.f : 0.f;
    float vy1 = (y1 >= 0 && y1 < H_) ? 1.f : 0.f;
    float vx0 = (x0 >= 0 && x0 < W_) ? 1.f : 0.f;
    float vx1 = (x1 >= 0 && x1 < W_) ? 1.f : 0.f;
    int cy0 = min(max(y0, 0), H_-1), cy1 = min(max(y1, 0), H_-1);
    int cx0 = min(max(x0, 0), W_-1), cx1 = min(max(x1, 0), W_-1);
    aS[0*128 + t] = cy0*W_ + cx0;
    aS[1*128 + t] = cy0*W_ + cx1;
    aS[2*128 + t] = cy1*W_ + cx0;
    aS[3*128 + t] = cy1*W_ + cx1;
    cS[0*128 + t] = (1.f-ly)*(1.f-lx)*vy0*vx0;
    cS[1*128 + t] = (1.f-ly)*lx      *vy0*vx1;
    cS[2*128 + t] = ly*(1.f-lx)      *vy1*vx0;
    cS[3*128 + t] = ly*lx            *vy1*vx1;
}

__global__ void __launch_bounds__(256, 2)
main_kernel(const float* __restrict__ x, float* __restrict__ out) {
    extern __shared__ float smem[];
    float* wS = smem + WS_OFF;                 // 2 * 4096 floats (per-tap, double-buffered)
    float* sS = smem + SS_OFF;                 // 2 * 8192 floats  [buf][c][w]
    float* cS = smem + CS_OFF;                 // 512 floats   [4][128]
    int*   aS = (int*)(smem + AS_OFF);         // 512 ints     [4][128]

    int b = blockIdx.x >> 7;
    int h = blockIdx.x & 127;
    int t = threadIdx.x;
    int wg = t & 31;       // 4-wide w group (lane)
    int og = t >> 5;       // 8-wide o group (warp)
    int w  = t & 127;      // gather w position (fixed per thread)
    int cbase = t >> 7;    // gather channel base (0 or 1)

    unsigned wS_base = (unsigned)__cvta_generic_to_shared(wS);

    // ---- issue cp.async for tap-0 weight tile into wS[0] ----
    {
        const float4* src = (const float4*)g_wT;   // tap 0 starts at 0
        #pragma unroll
        for (int i = 0; i < 4; i++) {
            int f4 = i*256 + t;                    // float4 index within 1024
            CP_ASYNC16(wS_base + f4*16, src + f4);
        }
        CP_COMMIT();
    }

    const float* xb = x + (size_t)b*C_*HW_;

    // Per-row offsets (threads 0..127, one per w)
    float o_t = 0.f, o_b = 0.f, o_l = 0.f, o_r = 0.f;
    if (t < 128) {
        int base = ((b*4 + 0)*H_ + h)*W_ + t;
        o_t = g_off[base];
        o_b = g_off[base +   HW_];
        o_l = g_off[base + 2*HW_];
        o_r = g_off[base + 3*HW_];
    }

    // accumulators: acc[p][j] = packed f32x2 (o = og*8+2p lo, og*8+2p+1 hi) at w = wg*4+j
    unsigned long long acc[4][4];
    #pragma unroll
    for (int p = 0; p < 4; p++)
        #pragma unroll
        for (int j = 0; j < 4; j++) acc[p][j] = 0ull;

    // ---- prologue: A(0) + pipelined gather of tap 0 into sS[0] ----
    if (t < 128) phaseA(0, h, t, o_t, o_b, o_l, o_r, cS, aS);
    __syncthreads();
    {
        float cc0 = cS[w], cc1 = cS[128+w], cc2 = cS[256+w], cc3 = cS[384+w];
        int   ia0 = aS[w], ia1 = aS[128+w], ia2 = aS[256+w], ia3 = aS[384+w];
        float pr[16];
        #pragma unroll 4
        for (int c = 0; c < 36; c++) {
            int slot = (c & 3) * 4;
            if (c >= 4) {
                int cg = cbase + 2*(c-4);
                sS[cg*128 + w] = cc0*pr[slot] + cc1*pr[slot+1] + cc2*pr[slot+2] + cc3*pr[slot+3];
            }
            if (c < 32) {
                const float* xp = xb + (size_t)(cbase + 2*c)*HW_;
                pr[slot]   = xp[ia0];
                pr[slot+1] = xp[ia1];
                pr[slot+2] = xp[ia2];
                pr[slot+3] = xp[ia3];
            }
        }
    }

    int cur = 0, curW = 0;
    #pragma unroll 1
    for (int k = 0; k < 9; k++) {
        CP_WAIT0();        // weight tile for tap k landed in wS[curW]
        __syncthreads();   // sS[cur] for tap k ready; cS/aS free for reuse
        bool act = (k < 8);
        if (act && t < 128) phaseA(k+1, h, t, o_t, o_b, o_l, o_r, cS, aS);
        __syncthreads();   // coeffs for tap k+1 visible

        float cc0 = 0.f, cc1 = 0.f, cc2 = 0.f, cc3 = 0.f;
        int   ia0 = 0,   ia1 = 0,   ia2 = 0,   ia3 = 0;
        if (act) {
            cc0 = cS[w]; cc1 = cS[128+w]; cc2 = cS[256+w]; cc3 = cS[384+w];
            ia0 = aS[w]; ia1 = aS[128+w]; ia2 = aS[256+w]; ia3 = aS[384+w];
        }
        const float4* sv4 = (const float4*)(sS + cur*8192);
        float*        sN  = sS + (cur^1)*8192;
        const float*  wk  = wS + curW*4096 + og*8;
        unsigned      wNext = wS_base + (curW^1)*4096*4;   // byte base of other buffer
        const float4* wsrc  = (const float4*)(g_wT + (k+1)*4096);
        float pr[16];

        // merged loop: GEMM(tap k) + dist-4 gather(tap k+1) + cp.async weights(tap k+1)
        #pragma unroll 4
        for (int c = 0; c < 64; c++) {
            int slot = (c & 3) * 4;
            if (act) {
                if (c >= 4 && c < 36) {
                    int cg = cbase + 2*(c-4);
                    sN[cg*128 + w] = cc0*pr[slot] + cc1*pr[slot+1] + cc2*pr[slot+2] + cc3*pr[slot+3];
                }
                if (c < 32) {
                    const float* xp = xb + (size_t)(cbase + 2*c)*HW_;
                    pr[slot]   = xp[ia0];
                    pr[slot+1] = xp[ia1];
                    pr[slot+2] = xp[ia2];
                    pr[slot+3] = xp[ia3];
                }
                if ((c & 15) == 8) {               // c = 8,24,40,56 -> 4 float4 per thread
                    int i = c >> 4;
                    int f4 = i*256 + t;
                    CP_ASYNC16(wNext + f4*16, wsrc + f4);
                }
            }
            // ---- GEMM c-iter (f32x2 packed) ----
            float4 s = sv4[c*32 + wg];
            const ulonglong2* wp2 = (const ulonglong2*)(wk + c*CO_);
            ulonglong2 wpa = wp2[0];   // packs (w_o0,w_o1),(w_o2,w_o3)
            ulonglong2 wpb = wp2[1];   // packs (w_o4,w_o5),(w_o6,w_o7)
            unsigned long long sd0, sd1, sd2, sd3;
            PACK_DUP(sd0, s.x); PACK_DUP(sd1, s.y); PACK_DUP(sd2, s.z); PACK_DUP(sd3, s.w);
            FMA2(acc[0][0], wpa.x, sd0); FMA2(acc[0][1], wpa.x, sd1);
            FMA2(acc[0][2], wpa.x, sd2); FMA2(acc[0][3], wpa.x, sd3);
            FMA2(acc[1][0], wpa.y, sd0); FMA2(acc[1][1], wpa.y, sd1);
            FMA2(acc[1][2], wpa.y, sd2); FMA2(acc[1][3], wpa.y, sd3);
            FMA2(acc[2][0], wpb.x, sd0); FMA2(acc[2][1], wpb.x, sd1);
            FMA2(acc[2][2], wpb.x, sd2); FMA2(acc[2][3], wpb.x, sd3);
            FMA2(acc[3][0], wpb.y, sd0); FMA2(acc[3][1], wpb.y, sd1);
            FMA2(acc[3][2], wpb.y, sd2); FMA2(acc[3][3], wpb.y, sd3);
        }
        CP_COMMIT();
        cur ^= 1; curW ^= 1;
    }

    // ---- write out: out[b][o][h][w], o = og*8 + 2p (lo) / 2p+1 (hi), w = wg*4+j ----
    size_t obase = (((size_t)b*CO_ + og*8)*H_ + h)*W_ + wg*4;
    #pragma unroll
    for (int p = 0; p < 4; p++) {
        float4 lo4, hi4;
        lo4.x = __uint_as_float((unsigned)(acc[p][0]));
        lo4.y = __uint_as_float((unsigned)(acc[p][1]));
        lo4.z = __uint_as_float((unsigned)(acc[p][2]));
        lo4.w = __uint_as_float((unsigned)(acc[p][3]));
        hi4.x = __uint_as_float((unsigned)(acc[p][0] >> 32));
        hi4.y = __uint_as_float((unsigned)(acc[p][1] >> 32));
        hi4.z = __uint_as_float((unsigned)(acc[p][2] >> 32));
        hi4.w = __uint_as_float((unsigned)(acc[p][3] >> 32));
        *(float4*)(out + obase + (size_t)(2*p    )*HW_) = lo4;
        *(float4*)(out + obase + (size_t)(2*p + 1)*HW_) = hi4;
    }
}

// ---------------------------------------------------------------- launch
extern "C" void kernel_launch(void* const* d_in, const int* in_sizes, int n_in,
                              void* d_out, int out_size) {
    const float* x  = (const float*)d_in[0];   // (8,64,128,128)
    const float* ow = (const float*)d_in[1];   // (4,64,3,3)
    const float* ob = (const float*)d_in[2];   // (4,)
    const float* wt = (const float*)d_in[3];   // (64,64,3,3)
    float* out = (float*)d_out;                // (8,64,128,128)

    cudaFuncSetAttribute(main_kernel, cudaFuncAttributeMaxDynamicSharedMemorySize,
                         SMEM_FLOATS * (int)sizeof(float));

    wT_kernel<<<(9*C_*CO_ + 255)/256, 256>>>(wt);
    offset_kernel<<<B_*H_, 128>>>(x, ow, ob);
    main_kernel<<<B_*H_, 256, SMEM_FLOATS * sizeof(float)>>>(x, out);
}

// round 4
// speedup vs baseline: 1.9321x; 1.0425x over previous
#include <cuda_runtime.h>

#define B_  8
#define C_  64
#define CO_ 64
#define H_  128
#define W_  128
#define HW_ (H_*W_)

// Scratch (device globals — no allocation allowed)
__device__ __align__(16) float g_off[B_*4*HW_];      // offsets o[b][4][h][w]
__device__ __align__(16) float g_wT[9*C_*CO_];       // weight transposed [k][c][o]

__constant__ int c_dysel[9] = {0,1,4,0,1,2,4,4,3};   // 0=t 1=b 2=l 3=r 4=zero
__constant__ int c_dxsel[9] = {4,0,1,4,2,2,4,3,3};

// packed fp32x2 FMA (SASS FFMA2) — PTX-only, ptxas never auto-fuses
#define FMA2(d,a,b) asm("fma.rn.f32x2 %0, %1, %2, %0;" : "+l"(d) : "l"(a), "l"(b))
#define PACK_DUP(d,f) asm("mov.b64 %0, {%1, %1};" : "=l"(d) : "r"(__float_as_uint(f)))

// cp.async 16B global->shared (no register cost, async completion)
#define CP_ASYNC16(saddr, gptr) \
    asm volatile("cp.async.cg.shared.global [%0], [%1], 16;" :: "r"(saddr), "l"(gptr) : "memory")
#define CP_COMMIT() asm volatile("cp.async.commit_group;" ::: "memory")
#define CP_WAIT0()  asm volatile("cp.async.wait_group 0;" ::: "memory")

// ---------------------------------------------------------------- weight transpose
__global__ void wT_kernel(const float* __restrict__ weight) {
    int idx = blockIdx.x*256 + threadIdx.x;
    if (idx < 9*C_*CO_) {
        int k = idx / (C_*CO_);
        int r = idx % (C_*CO_);
        int c = r / CO_;
        int o = r % CO_;
        g_wT[idx] = weight[(o*C_ + c)*9 + k];
    }
}

// ---------------------------------------------------------------- offset conv (4 out ch)
__global__ void offset_kernel(const float* __restrict__ x,
                              const float* __restrict__ ow,
                              const float* __restrict__ ob) {
    __shared__ float ws[4*C_*9];
    int b = blockIdx.x >> 7;
    int h = blockIdx.x & 127;
    int t = threadIdx.x;               // 128 threads: one per w
    for (int i = t; i < 4*C_*9; i += 128) ws[i] = ow[i];
    __syncthreads();

    float a0 = ob[0], a1 = ob[1], a2 = ob[2], a3 = ob[3];
    const float* xb = x + (size_t)b*C_*HW_;
    int w = t;
    for (int c = 0; c < C_; c++) {
        const float* xp = xb + c*HW_;
        #pragma unroll
        for (int i = 0; i < 3; i++) {
            int y = h - 1 + i;
            if ((unsigned)y >= (unsigned)H_) continue;
            #pragma unroll
            for (int j = 0; j < 3; j++) {
                int xx = w - 1 + j;
                if ((unsigned)xx >= (unsigned)W_) continue;
                float v = xp[y*W_ + xx];
                int kk = i*3 + j;
                a0 += v * ws[(0*C_ + c)*9 + kk];
                a1 += v * ws[(1*C_ + c)*9 + kk];
                a2 += v * ws[(2*C_ + c)*9 + kk];
                a3 += v * ws[(3*C_ + c)*9 + kk];
            }
        }
    }
    int base = ((b*4 + 0)*H_ + h)*W_ + w;
    g_off[base]          = a0;
    g_off[base +   HW_]  = a1;
    g_off[base + 2*HW_]  = a2;
    g_off[base + 3*HW_]  = a3;
}

// ---------------------------------------------------------------- main fused deformable conv
// smem (floats): wS double [2*4096) | sS double [2*8192) | cS [512) | aS(int) [512)
#define WS_OFF  0
#define SS_OFF  8192
#define CS_OFF  24576
#define AS_OFF  25088
#define SMEM_FLOATS 25600   // 100 KB -> 2 CTAs/SM

__device__ __forceinline__ float selo(int s, float t, float b, float l, float r) {
    switch (s) {
        case 0: return t;
        case 1: return b;
        case 2: return l;
        case 3: return r;
        default: return 0.f;
    }
}

__device__ __forceinline__ void phaseA(int k, int h, int t,
                                       float o_t, float o_b, float o_l, float o_r,
                                       float* cS, int* aS) {
    int ki = k / 3, kj = k % 3;
    float dy = selo(c_dysel[k], o_t, o_b, o_l, o_r);
    float dx = selo(c_dxsel[k], o_t, o_b, o_l, o_r);
    float py = (float)(h - 1 + ki) + dy;
    float px = (float)(t - 1 + kj) + dx;
    float y0f = floorf(py), x0f = floorf(px);
    float ly = py - y0f,   lx = px - x0f;
    int y0 = (int)y0f, x0 = (int)x0f;
    int y1 = y0 + 1,   x1 = x0 + 1;
    float vy0 = (y0 >= 0 && y0 < H_) ? 1.f : 0.f;
    float vy1 = (y1 >= 0 && y1 < H_) ? 1.f : 0.f;
    float vx0 = (x0 >= 0 && x0 < W_) ? 1.f : 0.f;
    float vx1 = (x1 >= 0 && x1 < W_) ? 1.f : 0.f;
    int cy0 = min(max(y0, 0), H_-1), cy1 = min(max(y1, 0), H_-1);
    int cx0 = min(max(x0, 0), W_-1), cx1 = min(max(x1, 0), W_-1);
    aS[0*128 + t] = cy0*W_ + cx0;
    aS[1*128 + t] = cy0*W_ + cx1;
    aS[2*128 + t] = cy1*W_ + cx0;
    aS[3*128 + t] = cy1*W_ + cx1;
    cS[0*128 + t] = (1.f-ly)*(1.f-lx)*vy0*vx0;
    cS[1*128 + t] = (1.f-ly)*lx      *vy0*vx1;
    cS[2*128 + t] = ly*(1.f-lx)      *vy1*vx0;
    cS[3*128 + t] = ly*lx            *vy1*vx1;
}

__global__ void __launch_bounds__(256, 2)
main_kernel(const float* __restrict__ x, float* __restrict__ out) {
    extern __shared__ float smem[];
    float* wS = smem + WS_OFF;                 // 2 * 4096 floats (per-tap, double-buffered)
    float* sS = smem + SS_OFF;                 // 2 * 8192 floats  [buf][c][w]
    float* cS = smem + CS_OFF;                 // 512 floats   [4][128]
    int*   aS = (int*)(smem + AS_OFF);         // 512 ints     [4][128]

    int b = blockIdx.x >> 7;
    int h = blockIdx.x & 127;
    int t = threadIdx.x;
    int wg = t & 31;       // 4-wide w group (lane)
    int og = t >> 5;       // 8-wide o group (warp)
    int w  = t & 127;      // gather w position (fixed per thread)
    int cbase = t >> 7;    // gather channel base (0 or 1)

    unsigned wS_base = (unsigned)__cvta_generic_to_shared(wS);

    // ---- issue cp.async for tap-0 weight tile into wS[0] ----
    {
        const float4* src = (const float4*)g_wT;   // tap 0 starts at 0
        #pragma unroll
        for (int i = 0; i < 4; i++) {
            int f4 = i*256 + t;                    // float4 index within 1024
            CP_ASYNC16(wS_base + f4*16, src + f4);
        }
        CP_COMMIT();
    }

    const float* xb = x + (size_t)b*C_*HW_;

    // Per-row offsets (threads 0..127, one per w)
    float o_t = 0.f, o_b = 0.f, o_l = 0.f, o_r = 0.f;
    if (t < 128) {
        int base = ((b*4 + 0)*H_ + h)*W_ + t;
        o_t = g_off[base];
        o_b = g_off[base +   HW_];
        o_l = g_off[base + 2*HW_];
        o_r = g_off[base + 3*HW_];
    }

    // accumulators: acc[p][j] = packed f32x2 (o = og*8+2p lo, og*8+2p+1 hi) at w = wg*4+j
    unsigned long long acc[4][4];
    #pragma unroll
    for (int p = 0; p < 4; p++)
        #pragma unroll
        for (int j = 0; j < 4; j++) acc[p][j] = 0ull;

    // ---- prologue: A(0) + distance-8 pipelined gather of tap 0 into sS[0] ----
    if (t < 128) phaseA(0, h, t, o_t, o_b, o_l, o_r, cS, aS);
    __syncthreads();
    {
        float cc0 = cS[w], cc1 = cS[128+w], cc2 = cS[256+w], cc3 = cS[384+w];
        int   ia0 = aS[w], ia1 = aS[128+w], ia2 = aS[256+w], ia3 = aS[384+w];
        float pr[32];
        #pragma unroll 8
        for (int c = 0; c < 40; c++) {
            int slot = (c & 7) * 4;
            if (c >= 8) {
                int cg = cbase + 2*(c-8);
                sS[cg*128 + w] = cc0*pr[slot] + cc1*pr[slot+1] + cc2*pr[slot+2] + cc3*pr[slot+3];
            }
            if (c < 32) {
                const float* xp = xb + (size_t)(cbase + 2*c)*HW_;
                pr[slot]   = xp[ia0];
                pr[slot+1] = xp[ia1];
                pr[slot+2] = xp[ia2];
                pr[slot+3] = xp[ia3];
            }
        }
    }

    int cur = 0, curW = 0;
    #pragma unroll 1
    for (int k = 0; k < 9; k++) {
        CP_WAIT0();        // weight tile for tap k landed in wS[curW]
        __syncthreads();   // sS[cur] for tap k ready; cS/aS free for reuse
        bool act = (k < 8);
        if (act && t < 128) phaseA(k+1, h, t, o_t, o_b, o_l, o_r, cS, aS);
        __syncthreads();   // coeffs for tap k+1 visible

        float cc0 = 0.f, cc1 = 0.f, cc2 = 0.f, cc3 = 0.f;
        int   ia0 = 0,   ia1 = 0,   ia2 = 0,   ia3 = 0;
        if (act) {
            cc0 = cS[w]; cc1 = cS[128+w]; cc2 = cS[256+w]; cc3 = cS[384+w];
            ia0 = aS[w]; ia1 = aS[128+w]; ia2 = aS[256+w]; ia3 = aS[384+w];
        }
        const float4* sv4 = (const float4*)(sS + cur*8192);
        float*        sN  = sS + (cur^1)*8192;
        const float*  wk  = wS + curW*4096 + og*8;
        unsigned      wNext = wS_base + (curW^1)*4096*4;   // byte base of other buffer
        const float4* wsrc  = (const float4*)(g_wT + (k+1)*4096);
        float pr[32];

        // merged loop: GEMM(tap k) + dist-8 gather(tap k+1) + cp.async weights(tap k+1)
        #pragma unroll 8
        for (int c = 0; c < 64; c++) {
            int slot = (c & 7) * 4;
            if (act) {
                if (c >= 8 && c < 40) {
                    int cg = cbase + 2*(c-8);
                    sN[cg*128 + w] = cc0*pr[slot] + cc1*pr[slot+1] + cc2*pr[slot+2] + cc3*pr[slot+3];
                }
                if (c < 32) {
                    const float* xp = xb + (size_t)(cbase + 2*c)*HW_;
                    pr[slot]   = xp[ia0];
                    pr[slot+1] = xp[ia1];
                    pr[slot+2] = xp[ia2];
                    pr[slot+3] = xp[ia3];
                }
                if ((c & 15) == 4) {               // c = 4,20,36,52 -> 4 float4 per thread
                    int i = c >> 4;
                    int f4 = i*256 + t;
                    CP_ASYNC16(wNext + f4*16, wsrc + f4);
                }
            }
            // ---- GEMM c-iter (f32x2 packed) ----
            float4 s = sv4[c*32 + wg];
            const ulonglong2* wp2 = (const ulonglong2*)(wk + c*CO_);
            ulonglong2 wpa = wp2[0];   // packs (w_o0,w_o1),(w_o2,w_o3)
            ulonglong2 wpb = wp2[1];   // packs (w_o4,w_o5),(w_o6,w_o7)
            unsigned long long sd0, sd1, sd2, sd3;
            PACK_DUP(sd0, s.x); PACK_DUP(sd1, s.y); PACK_DUP(sd2, s.z); PACK_DUP(sd3, s.w);
            FMA2(acc[0][0], wpa.x, sd0); FMA2(acc[0][1], wpa.x, sd1);
            FMA2(acc[0][2], wpa.x, sd2); FMA2(acc[0][3], wpa.x, sd3);
            FMA2(acc[1][0], wpa.y, sd0); FMA2(acc[1][1], wpa.y, sd1);
            FMA2(acc[1][2], wpa.y, sd2); FMA2(acc[1][3], wpa.y, sd3);
            FMA2(acc[2][0], wpb.x, sd0); FMA2(acc[2][1], wpb.x, sd1);
            FMA2(acc[2][2], wpb.x, sd2); FMA2(acc[2][3], wpb.x, sd3);
            FMA2(acc[3][0], wpb.y, sd0); FMA2(acc[3][1], wpb.y, sd1);
            FMA2(acc[3][2], wpb.y, sd2); FMA2(acc[3][3], wpb.y, sd3);
        }
        CP_COMMIT();
        cur ^= 1; curW ^= 1;
    }

    // ---- write out: out[b][o][h][w], o = og*8 + 2p (lo) / 2p+1 (hi), w = wg*4+j ----
    size_t obase = (((size_t)b*CO_ + og*8)*H_ + h)*W_ + wg*4;
    #pragma unroll
    for (int p = 0; p < 4; p++) {
        float4 lo4, hi4;
        lo4.x = __uint_as_float((unsigned)(acc[p][0]));
        lo4.y = __uint_as_float((unsigned)(acc[p][1]));
        lo4.z = __uint_as_float((unsigned)(acc[p][2]));
        lo4.w = __uint_as_float((unsigned)(acc[p][3]));
        hi4.x = __uint_as_float((unsigned)(acc[p][0] >> 32));
        hi4.y = __uint_as_float((unsigned)(acc[p][1] >> 32));
        hi4.z = __uint_as_float((unsigned)(acc[p][2] >> 32));
        hi4.w = __uint_as_float((unsigned)(acc[p][3] >> 32));
        *(float4*)(out + obase + (size_t)(2*p    )*HW_) = lo4;
        *(float4*)(out + obase + (size_t)(2*p + 1)*HW_) = hi4;
    }
}

// ---------------------------------------------------------------- launch
extern "C" void kernel_launch(void* const* d_in, const int* in_sizes, int n_in,
                              void* d_out, int out_size) {
    const float* x  = (const float*)d_in[0];   // (8,64,128,128)
    const float* ow = (const float*)d_in[1];   // (4,64,3,3)
    const float* ob = (const float*)d_in[2];   // (4,)
    const float* wt = (const float*)d_in[3];   // (64,64,3,3)
    float* out = (float*)d_out;                // (8,64,128,128)

    cudaFuncSetAttribute(main_kernel, cudaFuncAttributeMaxDynamicSharedMemorySize,
                         SMEM_FLOATS * (int)sizeof(float));

    wT_kernel<<<(9*C_*CO_ + 255)/256, 256>>>(wt);
    offset_kernel<<<B_*H_, 128>>>(x, ow, ob);
    main_kernel<<<B_*H_, 256, SMEM_FLOATS * sizeof(float)>>>(x, out);
}

// round 5
// speedup vs baseline: 2.1628x; 1.1194x over previous
#include <cuda_runtime.h>

#define B_  8
#define C_  64
#define CO_ 64
#define H_  128
#define W_  128
#define HW_ (H_*W_)

// Scratch (device globals — no allocation allowed)
__device__ __align__(16) float g_off[B_*4*HW_];      // offsets o[b][4][h][w]
__device__ __align__(16) float g_wT[9*C_*CO_];       // weight transposed [k][c][o]

__constant__ int c_dysel[9] = {0,1,4,0,1,2,4,4,3};   // 0=t 1=b 2=l 3=r 4=zero
__constant__ int c_dxsel[9] = {4,0,1,4,2,2,4,3,3};

// packed fp32x2 FMA (SASS FFMA2) — PTX-only
#define FMA2(d,a,b) asm("fma.rn.f32x2 %0, %1, %2, %0;" : "+l"(d) : "l"(a), "l"(b))
#define PACK_DUP(d,f) asm("mov.b64 %0, {%1, %1};" : "=l"(d) : "r"(__float_as_uint(f)))

// cp.async 16B global->shared
#define CP_ASYNC16(saddr, gptr) \
    asm volatile("cp.async.cg.shared.global [%0], [%1], 16;" :: "r"(saddr), "l"(gptr) : "memory")
#define CP_COMMIT() asm volatile("cp.async.commit_group;" ::: "memory")
#define CP_WAIT0()  asm volatile("cp.async.wait_group 0;" ::: "memory")

// ---------------------------------------------------------------- weight transpose
__global__ void wT_kernel(const float* __restrict__ weight) {
    int idx = blockIdx.x*256 + threadIdx.x;
    if (idx < 9*C_*CO_) {
        int k = idx / (C_*CO_);
        int r = idx % (C_*CO_);
        int c = r / CO_;
        int o = r % CO_;
        g_wT[idx] = weight[(o*C_ + c)*9 + k];
    }
}

// ---------------------------------------------------------------- offset conv (4 out ch)
__global__ void offset_kernel(const float* __restrict__ x,
                              const float* __restrict__ ow,
                              const float* __restrict__ ob) {
    __shared__ float ws[4*C_*9];
    int b = blockIdx.x >> 7;
    int h = blockIdx.x & 127;
    int t = threadIdx.x;               // 128 threads: one per w
    for (int i = t; i < 4*C_*9; i += 128) ws[i] = ow[i];
    __syncthreads();

    float a0 = ob[0], a1 = ob[1], a2 = ob[2], a3 = ob[3];
    const float* xb = x + (size_t)b*C_*HW_;
    int w = t;
    for (int c = 0; c < C_; c++) {
        const float* xp = xb + c*HW_;
        #pragma unroll
        for (int i = 0; i < 3; i++) {
            int y = h - 1 + i;
            if ((unsigned)y >= (unsigned)H_) continue;
            #pragma unroll
            for (int j = 0; j < 3; j++) {
                int xx = w - 1 + j;
                if ((unsigned)xx >= (unsigned)W_) continue;
                float v = xp[y*W_ + xx];
                int kk = i*3 + j;
                a0 += v * ws[(0*C_ + c)*9 + kk];
                a1 += v * ws[(1*C_ + c)*9 + kk];
                a2 += v * ws[(2*C_ + c)*9 + kk];
                a3 += v * ws[(3*C_ + c)*9 + kk];
            }
        }
    }
    int base = ((b*4 + 0)*H_ + h)*W_ + w;
    g_off[base]          = a0;
    g_off[base +   HW_]  = a1;
    g_off[base + 2*HW_]  = a2;
    g_off[base + 3*HW_]  = a3;
}

// ---------------------------------------------------------------- main fused deformable conv
// smem (floats): wS double [2*4096) | sS half-tile double [2*4096)  = 64 KB -> 3 CTAs/SM
#define SMEM_FLOATS 16384

__device__ __forceinline__ float selo(int s, float t, float b, float l, float r) {
    switch (s) {
        case 0: return t;
        case 1: return b;
        case 2: return l;
        case 3: return r;
        default: return 0.f;
    }
}

// Per-thread bilinear setup for tap k at (h, w): one base index into the row-
// image plus remapped 2x2-block coefficients (algebraically identical to the
// clamped 4-corner form; all 4 loads are in-bounds at base,+1,+W,+W+1).
__device__ __forceinline__ void phaseA_reg(int k, int h, int w,
                                           float o_t, float o_b, float o_l, float o_r,
                                           int& base, float& q00, float& q01,
                                           float& q10, float& q11) {
    int ki = k / 3, kj = k % 3;
    float dy = selo(c_dysel[k], o_t, o_b, o_l, o_r);
    float dx = selo(c_dxsel[k], o_t, o_b, o_l, o_r);
    float py = (float)(h - 1 + ki) + dy;
    float px = (float)(w - 1 + kj) + dx;
    float yf = floorf(py), xf = floorf(px);
    float ly = py - yf,   lx = px - xf;
    int y0 = (int)yf, x0 = (int)xf;
    int yb = min(max(y0, 0), H_-2);
    int xb = min(max(x0, 0), W_-2);
    float cy0 = (y0 == yb) ? (1.f - ly) : ((y0 == -1)   ? ly        : 0.f);
    float cy1 = (y0 == yb) ? ly         : ((y0 == H_-1) ? (1.f - ly) : 0.f);
    float cx0 = (x0 == xb) ? (1.f - lx) : ((x0 == -1)   ? lx        : 0.f);
    float cx1 = (x0 == xb) ? lx         : ((x0 == W_-1) ? (1.f - lx) : 0.f);
    q00 = cy0*cx0; q01 = cy0*cx1; q10 = cy1*cx0; q11 = cy1*cx1;
    base = yb*W_ + xb;
}

__global__ void __launch_bounds__(256, 3)
main_kernel(const float* __restrict__ x, float* __restrict__ out) {
    extern __shared__ float smem[];
    float* wS = smem;              // 2 * 4096 floats (per-tap weights, double-buffered)
    float* sS = smem + 8192;       // 2 * 4096 floats (half-tile samples: [32 c][128 w])

    int b = blockIdx.x >> 7;
    int h = blockIdx.x & 127;
    int t = threadIdx.x;
    int wg = t & 31;       // 4-wide w group (lane)
    int og = t >> 5;       // 8-wide o group (warp)
    int w  = t & 127;      // gather w position
    int cb = t >> 7;       // gather channel base (0 or 1)

    unsigned wS_base = (unsigned)__cvta_generic_to_shared(wS);

    // ---- cp.async tap-0 weight tile into wS[0] ----
    {
        const float4* src = (const float4*)g_wT;
        #pragma unroll
        for (int i = 0; i < 4; i++) {
            int f4 = i*256 + t;
            CP_ASYNC16(wS_base + f4*16, src + f4);
        }
        CP_COMMIT();
    }

    const float* xb = x + (size_t)b*C_*HW_;

    // Per-thread offsets (all 256 threads; pair t/t+128 duplicates)
    float o_t, o_b, o_l, o_r;
    {
        int ob_ = ((b*4 + 0)*H_ + h)*W_ + w;
        o_t = g_off[ob_];
        o_b = g_off[ob_ +   HW_];
        o_l = g_off[ob_ + 2*HW_];
        o_r = g_off[ob_ + 3*HW_];
    }

    // bilinear state for the tap currently being GATHERED
    int   gbase; float q00, q01, q10, q11;
    phaseA_reg(0, h, w, o_t, o_b, o_l, o_r, gbase, q00, q01, q10, q11);

    // accumulators: acc[p][j] = f32x2 (o = og*8+2p lo, +2p+1 hi) at w = wg*4+j
    unsigned long long acc[4][4];
    #pragma unroll
    for (int p = 0; p < 4; p++)
        #pragma unroll
        for (int j = 0; j < 4; j++) acc[p][j] = 0ull;

    float pr[16];   // distance-4 gather ring (4 slots x 4 corners)

    // ---- prologue: gather tap0 first half (c = cb+2i, i<16) into sS[0] ----
    {
        const float* gp = xb + (size_t)cb*HW_ + gbase;
        #pragma unroll
        for (int i = 0; i < 20; i++) {
            int slot = (i & 3) * 4;
            if (i >= 4) {
                int j = i - 4;
                sS[(cb + 2*j)*128 + w] = q00*pr[slot] + q01*pr[slot+1]
                                       + q10*pr[slot+2] + q11*pr[slot+3];
            }
            if (i < 16) {
                const float* p = gp + (size_t)(2*i)*HW_;
                pr[slot]   = p[0];
                pr[slot+1] = p[1];
                pr[slot+2] = p[W_];
                pr[slot+3] = p[W_+1];
            }
        }
    }

    // ---- 18 half-steps: GEMM(half s) overlapped with gather(half s+1) ----
    #pragma unroll 1
    for (int s = 0; s < 18; s++) {
        int k    = s >> 1;
        int half = s & 1;
        if (half == 0) CP_WAIT0();     // tap-k weights landed
        __syncthreads();               // sS[half] ready; sS[half^1] free

        bool has_g = (s < 17);
        if (half == 1 && has_g)        // entering tap k+1 on the gather side
            phaseA_reg(k+1, h, w, o_t, o_b, o_l, o_r, gbase, q00, q01, q10, q11);

        if (half == 0 && k < 8) {      // prefetch tap k+1 weights
            unsigned dstb = wS_base + ((k+1)&1)*4096*4;
            const float4* src = (const float4*)(g_wT + (k+1)*4096);
            #pragma unroll
            for (int i = 0; i < 4; i++) {
                int f4 = i*256 + t;
                CP_ASYNC16(dstb + f4*16, src + f4);
            }
        }

        const float4* sv4 = (const float4*)(sS + half*4096);
        float*        sN  = sS + (half^1)*4096;
        const float*  wk  = wS + (k&1)*4096 + half*32*CO_ + og*8;
        const float*  gp  = xb + (size_t)(((half^1)*32) + cb)*HW_ + gbase;

        #pragma unroll
        for (int c = 0; c < 32; c++) {
            if (has_g) {
                if ((c & 1) == 0) {                     // issue gather i = c/2
                    int i = c >> 1, slot = (i & 3)*4;
                    const float* p = gp + (size_t)(2*i)*HW_;
                    pr[slot]   = p[0];
                    pr[slot+1] = p[1];
                    pr[slot+2] = p[W_];
                    pr[slot+3] = p[W_+1];
                } else if (c >= 7) {                    // combine i = (c-7)/2
                    int i = (c - 7) >> 1, slot = (i & 3)*4;
                    sN[(cb + 2*i)*128 + w] = q00*pr[slot] + q01*pr[slot+1]
                                           + q10*pr[slot+2] + q11*pr[slot+3];
                }
            }
            // ---- GEMM c-iter (f32x2 packed) ----
            float4 sm = sv4[c*32 + wg];
            const ulonglong2* wp2 = (const ulonglong2*)(wk + c*CO_);
            ulonglong2 wpa = wp2[0];
            ulonglong2 wpb = wp2[1];
            unsigned long long sd0, sd1, sd2, sd3;
            PACK_DUP(sd0, sm.x); PACK_DUP(sd1, sm.y); PACK_DUP(sd2, sm.z); PACK_DUP(sd3, sm.w);
            FMA2(acc[0][0], wpa.x, sd0); FMA2(acc[0][1], wpa.x, sd1);
            FMA2(acc[0][2], wpa.x, sd2); FMA2(acc[0][3], wpa.x, sd3);
            FMA2(acc[1][0], wpa.y, sd0); FMA2(acc[1][1], wpa.y, sd1);
            FMA2(acc[1][2], wpa.y, sd2); FMA2(acc[1][3], wpa.y, sd3);
            FMA2(acc[2][0], wpb.x, sd0); FMA2(acc[2][1], wpb.x, sd1);
            FMA2(acc[2][2], wpb.x, sd2); FMA2(acc[2][3], wpb.x, sd3);
            FMA2(acc[3][0], wpb.y, sd0); FMA2(acc[3][1], wpb.y, sd1);
            FMA2(acc[3][2], wpb.y, sd2); FMA2(acc[3][3], wpb.y, sd3);
        }
        if (has_g) {                                    // tail combines i = 13,14,15
            #pragma unroll
            for (int i = 13; i < 16; i++) {
                int slot = (i & 3)*4;
                sN[(cb + 2*i)*128 + w] = q00*pr[slot] + q01*pr[slot+1]
                                       + q10*pr[slot+2] + q11*pr[slot+3];
            }
        }
        if (half == 0 && k < 8) CP_COMMIT();
    }

    // ---- write out: out[b][o][h][w], o = og*8 + 2p (lo) / 2p+1 (hi), w = wg*4+j ----
    size_t wbo = (((size_t)b*CO_ + og*8)*H_ + h)*W_ + wg*4;
    #pragma unroll
    for (int p = 0; p < 4; p++) {
        float4 lo4, hi4;
        lo4.x = __uint_as_float((unsigned)(acc[p][0]));
        lo4.y = __uint_as_float((unsigned)(acc[p][1]));
        lo4.z = __uint_as_float((unsigned)(acc[p][2]));
        lo4.w = __uint_as_float((unsigned)(acc[p][3]));
        hi4.x = __uint_as_float((unsigned)(acc[p][0] >> 32));
        hi4.y = __uint_as_float((unsigned)(acc[p][1] >> 32));
        hi4.z = __uint_as_float((unsigned)(acc[p][2] >> 32));
        hi4.w = __uint_as_float((unsigned)(acc[p][3] >> 32));
        *(float4*)(out + wbo + (size_t)(2*p    )*HW_) = lo4;
        *(float4*)(out + wbo + (size_t)(2*p + 1)*HW_) = hi4;
    }
}

// ---------------------------------------------------------------- launch
extern "C" void kernel_launch(void* const* d_in, const int* in_sizes, int n_in,
                              void* d_out, int out_size) {
    const float* x  = (const float*)d_in[0];   // (8,64,128,128)
    const float* ow = (const float*)d_in[1];   // (4,64,3,3)
    const float* ob = (const float*)d_in[2];   // (4,)
    const float* wt = (const float*)d_in[3];   // (64,64,3,3)
    float* out = (float*)d_out;                // (8,64,128,128)

    cudaFuncSetAttribute(main_kernel, cudaFuncAttributeMaxDynamicSharedMemorySize,
                         SMEM_FLOATS * (int)sizeof(float));

    wT_kernel<<<(9*C_*CO_ + 255)/256, 256>>>(wt);
    offset_kernel<<<B_*H_, 128>>>(x, ow, ob);
    main_kernel<<<B_*H_, 256, SMEM_FLOATS * sizeof(float)>>>(x, out);
}

// round 7
// speedup vs baseline: 2.6757x; 1.2372x over previous
#include <cuda_runtime.h>
#include <cuda_bf16.h>
#include <cstdint>

#define B_  8
#define C_  64
#define CO_ 64
#define H_  128
#define W_  128
#define HW_ (H_*W_)

// Scratch (device globals — no allocation allowed)
__device__ __align__(16)   float         g_off[B_*4*HW_];     // offsets o[b][4][h][w]
__device__ __align__(1024) __nv_bfloat16 g_wbf[9*2*4096];     // per tap: [hi 8KB][lo 8KB], SW128 [o][c]

__constant__ int c_dysel[9] = {0,1,4,0,1,2,4,4,3};   // 0=t 1=b 2=l 3=r 4=zero
__constant__ int c_dxsel[9] = {4,0,1,4,2,2,4,3,3};

// ---------------------------------------------------------------- PTX helpers (all sm_80+ baseline)
#define CP_ASYNC16(saddr, gptr) \
    asm volatile("cp.async.cg.shared.global [%0], [%1], 16;" :: "r"(saddr), "l"(gptr) : "memory")
#define CP_COMMIT()  asm volatile("cp.async.commit_group;" ::: "memory")
#define CP_WAIT(n)   asm volatile("cp.async.wait_group %0;" :: "n"(n) : "memory")

#define LDSM_X4(r0,r1,r2,r3, addr) \
    asm volatile("ldmatrix.sync.aligned.m8n8.x4.shared.b16 {%0,%1,%2,%3}, [%4];" \
                 : "=r"(r0), "=r"(r1), "=r"(r2), "=r"(r3) : "r"(addr))

// res = {lo half: bf16(lo), hi half: bf16(hi)}
#define CVT2(res, lo, hi) \
    asm("cvt.rn.bf16x2.f32 %0, %1, %2;" : "=r"(res) : "f"(hi), "f"(lo))

__device__ __forceinline__ void mma16816(float* d, const uint32_t* a, const uint32_t* b) {
    asm volatile("mma.sync.aligned.m16n8k16.row.col.f32.bf16.bf16.f32 "
        "{%0,%1,%2,%3}, {%4,%5,%6,%7}, {%8,%9}, {%0,%1,%2,%3};"
        : "+f"(d[0]), "+f"(d[1]), "+f"(d[2]), "+f"(d[3])
        : "r"(a[0]), "r"(a[1]), "r"(a[2]), "r"(a[3]), "r"(b[0]), "r"(b[1]));
}

__device__ __forceinline__ uint32_t s2u(const void* p) {
    uint32_t a;
    asm("{ .reg .u64 t; cvta.to.shared.u64 t, %1; cvt.u32.u64 %0, t; }" : "=r"(a) : "l"(p));
    return a;
}

__host__ __device__ __forceinline__ unsigned sw128(unsigned x) { return x ^ ((x >> 3) & 0x70); }

// ---------------------------------------------------------------- weight prep: bf16 hi/lo split, SW128 [o][c]
__global__ void wprep_kernel(const float* __restrict__ weight) {
    int idx = blockIdx.x*256 + threadIdx.x;       // 9*4096
    if (idx < 9*4096) {
        int k = idx >> 12;
        int r = idx & 4095;
        int o = r >> 6;
        int c = r & 63;
        float v = weight[(o*C_ + c)*9 + k];
        __nv_bfloat16 hb = __float2bfloat16(v);
        __nv_bfloat16 lb = __float2bfloat16(v - __bfloat162float(hb));
        unsigned so = sw128((unsigned)(o*128 + c*2));
        char* base = (char*)g_wbf + k*16384;
        *(__nv_bfloat16*)(base + so)        = hb;
        *(__nv_bfloat16*)(base + 8192 + so) = lb;
    }
}

// ---------------------------------------------------------------- offset conv (4 out ch)
__global__ void offset_kernel(const float* __restrict__ x,
                              const float* __restrict__ ow,
                              const float* __restrict__ ob) {
    __shared__ float ws[4*C_*9];
    int b = blockIdx.x >> 7;
    int h = blockIdx.x & 127;
    int t = threadIdx.x;
    for (int i = t; i < 4*C_*9; i += 128) ws[i] = ow[i];
    __syncthreads();

    float a0 = ob[0], a1 = ob[1], a2 = ob[2], a3 = ob[3];
    const float* xb = x + (size_t)b*C_*HW_;
    int w = t;
    for (int c = 0; c < C_; c++) {
        const float* xp = xb + c*HW_;
        #pragma unroll
        for (int i = 0; i < 3; i++) {
            int y = h - 1 + i;
            if ((unsigned)y >= (unsigned)H_) continue;
            #pragma unroll
            for (int j = 0; j < 3; j++) {
                int xx = w - 1 + j;
                if ((unsigned)xx >= (unsigned)W_) continue;
                float v = xp[y*W_ + xx];
                int kk = i*3 + j;
                a0 += v * ws[(0*C_ + c)*9 + kk];
                a1 += v * ws[(1*C_ + c)*9 + kk];
                a2 += v * ws[(2*C_ + c)*9 + kk];
                a3 += v * ws[(3*C_ + c)*9 + kk];
            }
        }
    }
    int base = ((b*4 + 0)*H_ + h)*W_ + w;
    g_off[base]          = a0;
    g_off[base +   HW_]  = a1;
    g_off[base + 2*HW_]  = a2;
    g_off[base + 3*HW_]  = a3;
}

// ---------------------------------------------------------------- bilinear setup (verified R5)
__device__ __forceinline__ float selo(int s, float t, float b, float l, float r) {
    switch (s) {
        case 0: return t;
        case 1: return b;
        case 2: return l;
        case 3: return r;
        default: return 0.f;
    }
}
__device__ __forceinline__ void phaseA_reg(int k, int h, int w,
                                           float o_t, float o_b, float o_l, float o_r,
                                           int& base, float& q00, float& q01,
                                           float& q10, float& q11) {
    int ki = k / 3, kj = k % 3;
    float dy = selo(c_dysel[k], o_t, o_b, o_l, o_r);
    float dx = selo(c_dxsel[k], o_t, o_b, o_l, o_r);
    float py = (float)(h - 1 + ki) + dy;
    float px = (float)(w - 1 + kj) + dx;
    float yf = floorf(py), xf = floorf(px);
    float ly = py - yf,   lx = px - xf;
    int y0 = (int)yf, x0 = (int)xf;
    int yb = min(max(y0, 0), H_-2);
    int xb = min(max(x0, 0), W_-2);
    float cy0 = (y0 == yb) ? (1.f - ly) : ((y0 == -1)   ? ly        : 0.f);
    float cy1 = (y0 == yb) ? ly         : ((y0 == H_-1) ? (1.f - ly) : 0.f);
    float cx0 = (x0 == xb) ? (1.f - lx) : ((x0 == -1)   ? lx        : 0.f);
    float cx1 = (x0 == xb) ? lx         : ((x0 == W_-1) ? (1.f - lx) : 0.f);
    q00 = cy0*cx0; q01 = cy0*cx1; q10 = cy1*cx0; q11 = cy1*cx1;
    base = yb*W_ + xb;
}

// ---------------------------------------------------------------- main mma.sync kernel
// smem bytes: Wbuf0 16K | Wbuf1 16K | Sh 16K | Sl 16K = 64 KB -> 2 CTAs/SM
#define SM_W0    0
#define SM_SH    32768
#define SM_SL    49152
#define SM_BYTES 65536

__global__ void __launch_bounds__(256, 2)
main_kernel(const float* __restrict__ x, float* __restrict__ out) {
    extern __shared__ char smem[];
    uint32_t sb = s2u(smem);
    char* ShP = smem + SM_SH;
    char* SlP = smem + SM_SL;

    int b = blockIdx.x >> 7;
    int h = blockIdx.x & 127;
    int t = threadIdx.x;
    int lane = t & 31;
    int wid  = t >> 5;
    int w    = t & 127;      // gather w position
    int cb   = t >> 7;       // gather channel half (0: c 0-31, 1: c 32-63)

    // warp tile: o range [otile, otile+16), w range [w0, w0+64)
    int otile = (wid & 3) * 16;
    int w0    = (wid >> 2) * 64;

    // ldmatrix per-lane row/offset precompute
    unsigned a_row  = otile + (lane & 15);                            // weights [o][c]
    unsigned a_koff = ((unsigned)lane >> 4) * 16;
    unsigned b_row  = w0 + (lane & 7) + (((unsigned)lane >> 4) & 1) * 8;  // samples [w][c]
    unsigned b_koff = (((unsigned)lane >> 3) & 1) * 16;

    // ---- cp.async tap-0 weights into Wbuf0 ----
    {
        const char* src = (const char*)g_wbf;
        #pragma unroll
        for (int i = 0; i < 4; i++) {
            int ch = i*256 + t;
            CP_ASYNC16(sb + SM_W0 + ch*16, src + ch*16);
        }
        CP_COMMIT();
    }

    const float* xb = x + (size_t)b*C_*HW_;
    float o_t, o_b, o_l, o_r;
    {
        int ob_ = ((b*4 + 0)*H_ + h)*W_ + w;
        o_t = g_off[ob_];
        o_b = g_off[ob_ +   HW_];
        o_l = g_off[ob_ + 2*HW_];
        o_r = g_off[ob_ + 3*HW_];
    }

    float acc[8][4];
    #pragma unroll
    for (int ni = 0; ni < 8; ni++)
        #pragma unroll
        for (int j = 0; j < 4; j++) acc[ni][j] = 0.f;

    #pragma unroll 1
    for (int k = 0; k < 9; k++) {
        __syncthreads();      // S tiles free (prev tap's MMA done); W buf (k+1)&1 free

        // prefetch weights for tap k+1
        if (k < 8) {
            const char* src = (const char*)g_wbf + (k+1)*16384;
            uint32_t dst = sb + SM_W0 + ((k+1)&1)*16384;
            #pragma unroll
            for (int i = 0; i < 4; i++) {
                int ch = i*256 + t;
                CP_ASYNC16(dst + ch*16, src + ch*16);
            }
            CP_COMMIT();
        }

        // ---- gather + bf16 hi/lo split into Sh/Sl (dist-4 LDG ring, pair-packed STS.32) ----
        {
            int gbase; float q00, q01, q10, q11;
            phaseA_reg(k, h, w, o_t, o_b, o_l, o_r, gbase, q00, q01, q10, q11);
            const float* gp = xb + (size_t)(cb*32)*HW_ + gbase;
            float pr[16];
            float vE = 0.f, lE = 0.f;
            #pragma unroll
            for (int i = 0; i < 36; i++) {
                int slot = (i & 3) * 4;
                if (i >= 4) {
                    int ii = i - 4;                 // channel index within half
                    float v = q00*pr[slot] + q01*pr[slot+1]
                            + q10*pr[slot+2] + q11*pr[slot+3];
                    float vh = __bfloat162float(__float2bfloat16(v));
                    float vl = v - vh;
                    if ((ii & 1) == 0) { vE = v; lE = vl; }
                    else {
                        int c0 = cb*32 + ii - 1;    // even channel of the pair
                        uint32_t hp, lp;
                        CVT2(hp, vE, v);
                        CVT2(lp, lE, vl);
                        unsigned off = sw128((unsigned)(w*128 + c0*2));
                        *(uint32_t*)(ShP + off) = hp;
                        *(uint32_t*)(SlP + off) = lp;
                    }
                }
                if (i < 32) {
                    const float* p = gp + (size_t)i*HW_;
                    pr[slot]   = p[0];
                    pr[slot+1] = p[1];
                    pr[slot+2] = p[W_];
                    pr[slot+3] = p[W_+1];
                }
            }
        }

        if (k < 8) { CP_WAIT(1); } else { CP_WAIT(0); }   // W(k) landed
        __syncthreads();                                  // S + W(k) visible CTA-wide

        // ---- MMA phase: 4 K-chunks x (Wh*Sh + Wl*Sh + Wh*Sl) ----
        uint32_t wb = sb + SM_W0 + (k&1)*16384;
        #pragma unroll
        for (int ks = 0; ks < 4; ks++) {
            unsigned aoff = sw128(a_row*128 + ks*32 + a_koff);
            uint32_t ah[4], al[4];
            LDSM_X4(ah[0], ah[1], ah[2], ah[3], wb + aoff);
            LDSM_X4(al[0], al[1], al[2], al[3], wb + 8192 + aoff);

            uint32_t bh[16];
            #pragma unroll
            for (int j = 0; j < 4; j++) {
                unsigned boff = sw128((b_row + j*16)*128 + ks*32 + b_koff);
                LDSM_X4(bh[4*j], bh[4*j+1], bh[4*j+2], bh[4*j+3], sb + SM_SH + boff);
            }
            #pragma unroll
            for (int ni = 0; ni < 8; ni++) mma16816(acc[ni], ah, &bh[ni*2]);
            #pragma unroll
            for (int ni = 0; ni < 8; ni++) mma16816(acc[ni], al, &bh[ni*2]);

            uint32_t bl[16];
            #pragma unroll
            for (int j = 0; j < 4; j++) {
                unsigned boff = sw128((b_row + j*16)*128 + ks*32 + b_koff);
                LDSM_X4(bl[4*j], bl[4*j+1], bl[4*j+2], bl[4*j+3], sb + SM_SL + boff);
            }
            #pragma unroll
            for (int ni = 0; ni < 8; ni++) mma16816(acc[ni], ah, &bl[ni*2]);
        }
    }

    // ---- epilogue: d[o][w] fragments -> out[b][o][h][w] (STG.64 over w pairs) ----
    {
        int o_r = otile + (lane >> 2);
        int w_c = w0 + (lane & 3) * 2;
        float* op = out + (((size_t)b*CO_ + o_r)*H_ + h)*W_ + w_c;
        #pragma unroll
        for (int ni = 0; ni < 8; ni++) {
            *(float2*)(op + ni*8)              = make_float2(acc[ni][0], acc[ni][1]);
            *(float2*)(op + 8*HW_ + ni*8)      = make_float2(acc[ni][2], acc[ni][3]);
        }
    }
}

// ---------------------------------------------------------------- launch
extern "C" void kernel_launch(void* const* d_in, const int* in_sizes, int n_in,
                              void* d_out, int out_size) {
    const float* x  = (const float*)d_in[0];   // (8,64,128,128)
    const float* ow = (const float*)d_in[1];   // (4,64,3,3)
    const float* ob = (const float*)d_in[2];   // (4,)
    const float* wt = (const float*)d_in[3];   // (64,64,3,3)
    float* out = (float*)d_out;                // (8,64,128,128)

    cudaFuncSetAttribute(main_kernel, cudaFuncAttributeMaxDynamicSharedMemorySize, SM_BYTES);

    wprep_kernel<<<(9*4096 + 255)/256, 256>>>(wt);
    offset_kernel<<<B_*H_, 128>>>(x, ow, ob);
    main_kernel<<<B_*H_, 256, SM_BYTES>>>(x, out);
}